// round 5
// baseline (speedup 1.0000x reference)
#include <cuda_runtime.h>

#define B_    128
#define NT    64
#define WIN   200
#define EMB_  128
#define NW_   128
#define TPB   320

typedef unsigned long long ull;

#define NEG_INF (__int_as_float(0xff800000))

__device__ __forceinline__ ull fma2v(ull a, ull b, ull c) {
    ull d; asm("fma.rn.f32x2 %0, %1, %2, %3;" : "=l"(d) : "l"(a), "l"(b), "l"(c)); return d;
}
__device__ __forceinline__ ull pack2(float x, float y) {
    ull d; asm("mov.b64 %0, {%1, %2};" : "=l"(d) : "f"(x), "f"(y)); return d;
}
__device__ __forceinline__ float2 unpack2(ull a) {
    float2 r; asm("mov.b64 {%0, %1}, %2;" : "=f"(r.x), "=f"(r.y) : "l"(a)); return r;
}
// acc += relu2(hp + hq) * hw   (2 elements, packed f32x2; relu on ALU pipe)
__device__ __forceinline__ void relu_dot2(ull& acc, ull hp, ull hq, ull hw) {
    asm("{\n\t"
        ".reg .b64 s;\n\t"
        ".reg .f32 lo, hi;\n\t"
        "add.rn.f32x2 s, %1, %2;\n\t"
        "mov.b64 {lo, hi}, s;\n\t"
        "max.f32 lo, lo, 0f00000000;\n\t"
        "max.f32 hi, hi, 0f00000000;\n\t"
        "mov.b64 s, {lo, hi};\n\t"
        "fma.rn.f32x2 %0, s, %3, %0;\n\t"
        "}" : "+l"(acc) : "l"(hp), "l"(hq), "l"(hw));
}

// ---- shared memory layout (offsets in floats) ----
#define OFF_HQ    0
#define OFF_HP    25600
#define OFF_SCR   33792
#define OFF_SCRX  (OFF_SCR + 64*130)
#define OFF_HW    55112
#define OFF_MADD  55240
#define OFF_MISC  55440   /* [0]=rnorm [1]=hb [2]=mask-dtype flag */
#define OFF_TI    55444
#define OFF_CI    55508
#define SMEM_FLOATS 55712
#define SMEM_BYTES (SMEM_FLOATS * 4)

// Projection GEMM: outBuf[nc][r][c] = sum_e X[r][e] * W[n][wcol+e] (+Wb[n])
template<int IR, int R, bool ADD_WB>
__device__ __forceinline__ void proj(float* sm, const float* __restrict__ vecs,
                                     const float* __restrict__ Ww, int wcol,
                                     const float* __restrict__ Wb,
                                     float* outBuf, int pitch4, int tid)
{
    const int* items = (const int*)(sm + (R == WIN ? OFF_CI : OFF_TI));
    float* scrW = sm + OFF_SCR;   // [64][130]  W[e][n] transposed half
    float* scrX = sm + OFF_SCRX;  // [200][65]  gathered embeddings half
    ull acc[IR][8];
#pragma unroll
    for (int i = 0; i < IR; i++)
#pragma unroll
        for (int j = 0; j < 8; j++) acc[i][j] = 0ull;

    const int ww = tid % 40, tg = tid / 40;

    for (int eh = 0; eh < 2; ++eh) {
        const int e0 = eh * 64;
        for (int idx = tid; idx < 64 * 128; idx += TPB) {
            int n = idx >> 6, e = idx & 63;
            scrW[e * 130 + n] = Ww[n * 256 + wcol + e0 + e];
        }
        for (int idx = tid; idx < R * 64; idx += TPB) {
            int r = idx >> 6, e = idx & 63;
            scrX[r * 65 + e] = vecs[items[r] * EMB_ + e0 + e];
        }
        __syncthreads();
#pragma unroll 4
        for (int e = 0; e < 64; ++e) {
            ull w2[8];
#pragma unroll
            for (int j = 0; j < 8; j++)
                w2[j] = *(const ull*)(scrW + e * 130 + tg * 16 + 2 * j);
#pragma unroll
            for (int i = 0; i < IR; i++) {
                float xv = scrX[(ww + 40 * i) * 65 + e];
                ull xd = pack2(xv, xv);
#pragma unroll
                for (int j = 0; j < 8; j++) acc[i][j] = fma2v(xd, w2[j], acc[i][j]);
            }
        }
        __syncthreads();
    }
#pragma unroll
    for (int i = 0; i < IR; i++) {
        int r = ww + 40 * i;
        if (r < R) {
#pragma unroll
            for (int j = 0; j < 8; j++) {
                int n = tg * 16 + 2 * j;
                float2 a = unpack2(acc[i][j]);
                float b0 = ADD_WB ? __ldg(Wb + n) : 0.0f;
                float b1 = ADD_WB ? __ldg(Wb + n + 1) : 0.0f;
                outBuf[(n >> 2) * pitch4 + r * 4 + (n & 3)] = a.x + b0;
                outBuf[((n + 1) >> 2) * pitch4 + r * 4 + ((n + 1) & 3)] = a.y + b1;
            }
        }
    }
}

__global__ void __launch_bounds__(TPB, 1)
nais_kernel(const float* __restrict__ tvecs, const float* __restrict__ cvecs,
            const float* __restrict__ W_w, const float* __restrict__ W_b,
            const float* __restrict__ h_w, const float* __restrict__ h_b,
            const int* __restrict__ titems, const int* __restrict__ citems,
            const unsigned char* __restrict__ mask, float* __restrict__ out)
{
    extern __shared__ float sm[];
    const int tid = threadIdx.x;
    const int b = blockIdx.x;

    // ---- stage indices / small vectors ----
    if (tid < NT)  ((int*)(sm + OFF_TI))[tid] = titems[b * NT + tid];
    if (tid < WIN) ((int*)(sm + OFF_CI))[tid] = citems[b * WIN + tid];
    if (tid < NW_) sm[OFF_HW + tid] = h_w[tid];
    if (tid == 0) { sm[OFF_MISC + 1] = h_b[0]; ((int*)sm)[OFF_MISC + 2] = 0; }
    __syncthreads();

    // ---- mask dtype detection: scan first 25600 bytes as u32 words.
    // int32 bool (widened) -> every word is 0 or 1. packed bytes -> words
    // like 0x00010001 appear -> flag set. Deterministic per input.
    {
        const unsigned* mw = (const unsigned*)mask;
        int bad = 0;
        for (int i = tid; i < (B_ * WIN) / 4; i += TPB)
            if (mw[i] > 1u) bad = 1;
        if (bad) ((int*)sm)[OFF_MISC + 2] = 1;
    }
    __syncthreads();
    {
        const bool bytes_layout = ((int*)sm)[OFF_MISC + 2] != 0;
        if (tid < WIN) {
            int mv = bytes_layout ? (int)mask[b * WIN + tid]
                                  : ((const int*)mask)[b * WIN + tid];
            sm[OFF_MADD + tid] = mv ? NEG_INF : 0.0f;
        }
    }
    __syncthreads();

    if (tid < 32) {  // norm = (1000 - npad)^0.5 ; store reciprocal
        float c = 0.0f;
        for (int w = tid; w < WIN; w += 32) c += (sm[OFF_MADD + w] < 0.0f) ? 1.0f : 0.0f;
#pragma unroll
        for (int o = 16; o; o >>= 1) c += __shfl_xor_sync(0xffffffffu, c, o);
        if (tid == 0) sm[OFF_MISC] = 1.0f / sqrtf(1000.0f - c);
    }

    // ---- projections: hq = k·Wq^T + Wb ; hp = q·Wp^T ----
    proj<5, WIN, true >(sm, cvecs, W_w, EMB_, W_b, sm + OFF_HQ, WIN * 4, tid);
    __syncthreads();
    proj<2, NT,  false>(sm, tvecs, W_w, 0,    W_b, sm + OFF_HP, NT * 4, tid);
    __syncthreads();

    // ---- step 4: att[t][w] = sum_n relu(hp+hq)*hw ----
    {
        const int ww = tid % 40, tg = tid / 40;
        ull acc[5][8];
#pragma unroll
        for (int i = 0; i < 5; i++)
#pragma unroll
            for (int j = 0; j < 8; j++) acc[i][j] = 0ull;
        const ulonglong2* HWv = (const ulonglong2*)(sm + OFF_HW);
#pragma unroll 2
        for (int nc = 0; nc < 32; ++nc) {
            ulonglong2 hw = HWv[nc];
            ulonglong2 hqv[5], hpv[8];
#pragma unroll
            for (int i = 0; i < 5; i++)
                hqv[i] = *(const ulonglong2*)(sm + OFF_HQ + nc * 800 + (ww + 40 * i) * 4);
#pragma unroll
            for (int j = 0; j < 8; j++)
                hpv[j] = *(const ulonglong2*)(sm + OFF_HP + nc * 256 + (tg * 8 + j) * 4);
#pragma unroll
            for (int i = 0; i < 5; i++)
#pragma unroll
                for (int j = 0; j < 8; j++) {
                    relu_dot2(acc[i][j], hpv[j].x, hqv[i].x, hw.x);
                    relu_dot2(acc[i][j], hpv[j].y, hqv[i].y, hw.y);
                }
        }
        float* ATT = sm + OFF_SCR;
#pragma unroll
        for (int i = 0; i < 5; i++)
#pragma unroll
            for (int j = 0; j < 8; j++) {
                float2 a = unpack2(acc[i][j]);
                ATT[(tg * 8 + j) * WIN + ww + 40 * i] = a.x + a.y;
            }
    }
    __syncthreads();

    // ---- step 5: masked softmax over w, per t ----
    {
        float* ATT = sm + OFF_SCR;
        const int warp = tid >> 5, lane = tid & 31;
        for (int t = warp; t < NT; t += 10) {
            float v[7], p[7];
            float m = NEG_INF;
#pragma unroll
            for (int k = 0; k < 7; k++) {
                int w = lane + 32 * k;
                v[k] = (w < WIN) ? (ATT[t * WIN + w] + sm[OFF_MADD + w]) : NEG_INF;
                m = fmaxf(m, v[k]);
            }
#pragma unroll
            for (int o = 16; o; o >>= 1) m = fmaxf(m, __shfl_xor_sync(0xffffffffu, m, o));
            float s = 0.0f;
#pragma unroll
            for (int k = 0; k < 7; k++) { p[k] = __expf(v[k] - m); s += p[k]; }
#pragma unroll
            for (int o = 16; o; o >>= 1) s += __shfl_xor_sync(0xffffffffu, s, o);
            float inv = 1.0f / s;
#pragma unroll
            for (int k = 0; k < 7; k++) {
                int w = lane + 32 * k;
                if (w < WIN) ATT[t * WIN + w] = p[k] * inv;
            }
        }
    }
    __syncthreads();

    // ---- restage k into HQ area as [200][128] ----
    {
        float4* K4 = (float4*)(sm + OFF_HQ);
        const int* ci = (const int*)(sm + OFF_CI);
        for (int idx = tid; idx < WIN * 32; idx += TPB) {
            int w = idx >> 5, c = idx & 31;
            K4[w * 32 + c] = *(const float4*)(cvecs + ci[w] * EMB_ + c * 4);
        }
    }
    __syncthreads();

    // ---- step 6: out[t][e] = rnorm * sum_w att[t][w] * k[w][e] ----
    {
        const float* ATT = sm + OFF_SCR;
        const float* K = sm + OFF_HQ;
        const float rn = sm[OFF_MISC];
        const int ec = tid & 31, tt = tid >> 5;
        for (int t0 = 2 * tt; t0 < NT; t0 += 20) {
            ull a0 = 0, a1 = 0, c0 = 0, c1 = 0;
#pragma unroll 4
            for (int w = 0; w < WIN; ++w) {
                float x0 = ATT[t0 * WIN + w];
                float x1 = ATT[(t0 + 1) * WIN + w];
                ulonglong2 k2 = *(const ulonglong2*)(K + w * EMB_ + ec * 4);
                ull d0 = pack2(x0, x0), d1 = pack2(x1, x1);
                a0 = fma2v(d0, k2.x, a0); a1 = fma2v(d0, k2.y, a1);
                c0 = fma2v(d1, k2.x, c0); c1 = fma2v(d1, k2.y, c1);
            }
            float2 A0 = unpack2(a0), A1 = unpack2(a1), C0 = unpack2(c0), C1 = unpack2(c1);
            float4 o0 = make_float4(A0.x * rn, A0.y * rn, A1.x * rn, A1.y * rn);
            float4 o1 = make_float4(C0.x * rn, C0.y * rn, C1.x * rn, C1.y * rn);
            *(float4*)(out + ((size_t)b * NT + t0) * EMB_ + ec * 4) = o0;
            *(float4*)(out + ((size_t)b * NT + t0 + 1) * EMB_ + ec * 4) = o1;
        }
    }
}

extern "C" void kernel_launch(void* const* d_in, const int* in_sizes, int n_in,
                              void* d_out, int out_size)
{
    const float* tvecs = (const float*)d_in[0];
    const float* cvecs = (const float*)d_in[1];
    const float* W_w   = (const float*)d_in[2];
    const float* W_b   = (const float*)d_in[3];
    const float* h_w   = (const float*)d_in[4];
    const float* h_b   = (const float*)d_in[5];
    const int*   ti    = (const int*)d_in[6];
    const int*   ci    = (const int*)d_in[7];
    const unsigned char* mask = (const unsigned char*)d_in[8];

    cudaFuncSetAttribute(nais_kernel, cudaFuncAttributeMaxDynamicSharedMemorySize, SMEM_BYTES);
    nais_kernel<<<B_, TPB, SMEM_BYTES>>>(tvecs, cvecs, W_w, W_b, h_w, h_b,
                                         ti, ci, mask, (float*)d_out);
}

// round 6
// speedup vs baseline: 1.2343x; 1.2343x over previous
#include <cuda_runtime.h>

#define B_    128
#define NT    64
#define WIN   200
#define EMB_  128
#define NW_   128
#define TPB   640

typedef unsigned long long ull;

#define NEG_INF (__int_as_float(0xff800000))

__device__ __forceinline__ ull fma2v(ull a, ull b, ull c) {
    ull d; asm("fma.rn.f32x2 %0, %1, %2, %3;" : "=l"(d) : "l"(a), "l"(b), "l"(c)); return d;
}
__device__ __forceinline__ ull pack2(float x, float y) {
    ull d; asm("mov.b64 %0, {%1, %2};" : "=l"(d) : "f"(x), "f"(y)); return d;
}
__device__ __forceinline__ float2 unpack2(ull a) {
    float2 r; asm("mov.b64 {%0, %1}, %2;" : "=f"(r.x), "=f"(r.y) : "l"(a)); return r;
}
// acc += relu2(hp + hq) * hw   (2 lanes packed f32x2; relu on ALU pipe)
__device__ __forceinline__ void relu_dot2(ull& acc, ull hp, ull hq, ull hw) {
    asm("{\n\t"
        ".reg .b64 s;\n\t"
        ".reg .f32 lo, hi;\n\t"
        "add.rn.f32x2 s, %1, %2;\n\t"
        "mov.b64 {lo, hi}, s;\n\t"
        "max.f32 lo, lo, 0f00000000;\n\t"
        "max.f32 hi, hi, 0f00000000;\n\t"
        "mov.b64 s, {lo, hi};\n\t"
        "fma.rn.f32x2 %0, s, %3, %0;\n\t"
        "}" : "+l"(acc) : "l"(hp), "l"(hq), "l"(hw));
}

// ---- shared memory layout (offsets in floats) ----
#define OFF_HQ    0
#define OFF_HP    25600
#define OFF_SCR   33792
#define OFF_SCRX  (OFF_SCR + 64*130)
#define OFF_HW    55112
#define OFF_MADD  55240
#define OFF_MISC  55440   /* [0]=rnorm [1]=hb [2]=mask-dtype flag */
#define OFF_TI    55444
#define OFF_CI    55508
#define SMEM_FLOATS 55712
#define SMEM_BYTES (SMEM_FLOATS * 4)

// Projection GEMM: outBuf[nc][r][c] = sum_e X[r][e] * W[n][wcol+e] (+Wb[n])
// 640 threads: ww = tid%40 (row lane), tg = tid/40 in [0,16) -> 8 n each (4 f32x2)
template<int IR, int R, bool ADD_WB>
__device__ __forceinline__ void proj(float* sm, const float* __restrict__ vecs,
                                     const float* __restrict__ Ww, int wcol,
                                     const float* __restrict__ Wb,
                                     float* outBuf, int pitch4, int tid)
{
    const int* items = (const int*)(sm + (R == WIN ? OFF_CI : OFF_TI));
    float* scrW = sm + OFF_SCR;   // [64][130]  W[e][n] transposed half
    float* scrX = sm + OFF_SCRX;  // [200][65]  gathered embeddings half
    ull acc[IR][4];
#pragma unroll
    for (int i = 0; i < IR; i++)
#pragma unroll
        for (int j = 0; j < 4; j++) acc[i][j] = 0ull;

    const int ww = tid % 40, tg = tid / 40;

    for (int eh = 0; eh < 2; ++eh) {
        const int e0 = eh * 64;
        for (int idx = tid; idx < 64 * 128; idx += TPB) {
            int n = idx >> 6, e = idx & 63;
            scrW[e * 130 + n] = Ww[n * 256 + wcol + e0 + e];
        }
        for (int idx = tid; idx < R * 64; idx += TPB) {
            int r = idx >> 6, e = idx & 63;
            scrX[r * 65 + e] = vecs[items[r] * EMB_ + e0 + e];
        }
        __syncthreads();
#pragma unroll 4
        for (int e = 0; e < 64; ++e) {
            ull w2[4];
#pragma unroll
            for (int j = 0; j < 4; j++)
                w2[j] = *(const ull*)(scrW + e * 130 + tg * 8 + 2 * j);
#pragma unroll
            for (int i = 0; i < IR; i++) {
                float xv = scrX[(ww + 40 * i) * 65 + e];
                ull xd = pack2(xv, xv);
#pragma unroll
                for (int j = 0; j < 4; j++) acc[i][j] = fma2v(xd, w2[j], acc[i][j]);
            }
        }
        __syncthreads();
    }
#pragma unroll
    for (int i = 0; i < IR; i++) {
        int r = ww + 40 * i;
        if (r < R) {
#pragma unroll
            for (int j = 0; j < 4; j++) {
                int n = tg * 8 + 2 * j;
                float2 a = unpack2(acc[i][j]);
                float b0 = ADD_WB ? __ldg(Wb + n) : 0.0f;
                float b1 = ADD_WB ? __ldg(Wb + n + 1) : 0.0f;
                outBuf[(n >> 2) * pitch4 + r * 4 + (n & 3)] = a.x + b0;
                outBuf[((n + 1) >> 2) * pitch4 + r * 4 + ((n + 1) & 3)] = a.y + b1;
            }
        }
    }
}

__global__ void __launch_bounds__(TPB, 1)
nais_kernel(const float* __restrict__ tvecs, const float* __restrict__ cvecs,
            const float* __restrict__ W_w, const float* __restrict__ W_b,
            const float* __restrict__ h_w, const float* __restrict__ h_b,
            const int* __restrict__ titems, const int* __restrict__ citems,
            const unsigned char* __restrict__ mask, float* __restrict__ out)
{
    extern __shared__ float sm[];
    const int tid = threadIdx.x;
    const int b = blockIdx.x;

    // ---- stage indices / small vectors ----
    if (tid < NT)  ((int*)(sm + OFF_TI))[tid] = titems[b * NT + tid];
    if (tid < WIN) ((int*)(sm + OFF_CI))[tid] = citems[b * WIN + tid];
    if (tid < NW_) sm[OFF_HW + tid] = h_w[tid];
    if (tid == 0) { sm[OFF_MISC + 1] = h_b[0]; ((int*)sm)[OFF_MISC + 2] = 0; }
    __syncthreads();

    // ---- mask dtype detection (int32-widened bool vs packed bytes) ----
    {
        const unsigned* mw = (const unsigned*)mask;
        int bad = 0;
        for (int i = tid; i < (B_ * WIN) / 4; i += TPB)
            if (mw[i] > 1u) bad = 1;
        if (bad) ((int*)sm)[OFF_MISC + 2] = 1;
    }
    __syncthreads();
    {
        const bool bytes_layout = ((int*)sm)[OFF_MISC + 2] != 0;
        if (tid < WIN) {
            int mv = bytes_layout ? (int)mask[b * WIN + tid]
                                  : ((const int*)mask)[b * WIN + tid];
            sm[OFF_MADD + tid] = mv ? NEG_INF : 0.0f;
        }
    }
    __syncthreads();

    if (tid < 32) {  // rnorm = (1000 - npad)^-0.5
        float c = 0.0f;
        for (int w = tid; w < WIN; w += 32) c += (sm[OFF_MADD + w] < 0.0f) ? 1.0f : 0.0f;
#pragma unroll
        for (int o = 16; o; o >>= 1) c += __shfl_xor_sync(0xffffffffu, c, o);
        if (tid == 0) sm[OFF_MISC] = 1.0f / sqrtf(1000.0f - c);
    }

    // ---- projections: hq = k·Wq^T + Wb ; hp = q·Wp^T ----
    proj<5, WIN, true >(sm, cvecs, W_w, EMB_, W_b, sm + OFF_HQ, WIN * 4, tid);
    __syncthreads();
    proj<2, NT,  false>(sm, tvecs, W_w, 0,    W_b, sm + OFF_HP, NT * 4, tid);
    __syncthreads();

    // ---- step 4: att[t][w] = sum_n relu(hp+hq)*hw ----
    // 640 threads: ww = tid%40 (5 w each), tg = tid/40 in [0,16) (4 t each)
    {
        const int ww = tid % 40, tg = tid / 40;
        ull acc[5][4];
#pragma unroll
        for (int i = 0; i < 5; i++)
#pragma unroll
            for (int j = 0; j < 4; j++) acc[i][j] = 0ull;
        const ulonglong2* HWv = (const ulonglong2*)(sm + OFF_HW);
#pragma unroll 2
        for (int nc = 0; nc < 32; ++nc) {
            ulonglong2 hw = HWv[nc];
            ulonglong2 hqv[5], hpv[4];
#pragma unroll
            for (int i = 0; i < 5; i++)
                hqv[i] = *(const ulonglong2*)(sm + OFF_HQ + nc * 800 + (ww + 40 * i) * 4);
#pragma unroll
            for (int j = 0; j < 4; j++)
                hpv[j] = *(const ulonglong2*)(sm + OFF_HP + nc * 256 + (tg * 4 + j) * 4);
#pragma unroll
            for (int i = 0; i < 5; i++)
#pragma unroll
                for (int j = 0; j < 4; j++) {
                    relu_dot2(acc[i][j], hpv[j].x, hqv[i].x, hw.x);
                    relu_dot2(acc[i][j], hpv[j].y, hqv[i].y, hw.y);
                }
        }
        float* ATT = sm + OFF_SCR;
#pragma unroll
        for (int i = 0; i < 5; i++)
#pragma unroll
            for (int j = 0; j < 4; j++) {
                float2 a = unpack2(acc[i][j]);
                ATT[(tg * 4 + j) * WIN + ww + 40 * i] = a.x + a.y;
            }
    }
    __syncthreads();

    // ---- step 5: masked softmax over w, per t (20 warps) ----
    {
        float* ATT = sm + OFF_SCR;
        const int warp = tid >> 5, lane = tid & 31;
        for (int t = warp; t < NT; t += 20) {
            float v[7], p[7];
            float m = NEG_INF;
#pragma unroll
            for (int k = 0; k < 7; k++) {
                int w = lane + 32 * k;
                v[k] = (w < WIN) ? (ATT[t * WIN + w] + sm[OFF_MADD + w]) : NEG_INF;
                m = fmaxf(m, v[k]);
            }
#pragma unroll
            for (int o = 16; o; o >>= 1) m = fmaxf(m, __shfl_xor_sync(0xffffffffu, m, o));
            float s = 0.0f;
#pragma unroll
            for (int k = 0; k < 7; k++) { p[k] = __expf(v[k] - m); s += p[k]; }
#pragma unroll
            for (int o = 16; o; o >>= 1) s += __shfl_xor_sync(0xffffffffu, s, o);
            float inv = 1.0f / s;
#pragma unroll
            for (int k = 0; k < 7; k++) {
                int w = lane + 32 * k;
                if (w < WIN) ATT[t * WIN + w] = p[k] * inv;
            }
        }
    }
    __syncthreads();

    // ---- restage k into HQ area as [200][128] ----
    {
        float4* K4 = (float4*)(sm + OFF_HQ);
        const int* ci = (const int*)(sm + OFF_CI);
        for (int idx = tid; idx < WIN * 32; idx += TPB) {
            int w = idx >> 5, c = idx & 31;
            K4[w * 32 + c] = *(const float4*)(cvecs + ci[w] * EMB_ + c * 4);
        }
    }
    __syncthreads();

    // ---- step 6: out[t][e] = rnorm * sum_w att[t][w] * k[w][e] (20 warps) ----
    {
        const float* ATT = sm + OFF_SCR;
        const float* K = sm + OFF_HQ;
        const float rn = sm[OFF_MISC];
        const int ec = tid & 31, tt = tid >> 5;
        for (int t0 = 2 * tt; t0 < NT; t0 += 40) {
            ull a0 = 0, a1 = 0, c0 = 0, c1 = 0;
#pragma unroll 4
            for (int w = 0; w < WIN; ++w) {
                float x0 = ATT[t0 * WIN + w];
                float x1 = ATT[(t0 + 1) * WIN + w];
                ulonglong2 k2 = *(const ulonglong2*)(K + w * EMB_ + ec * 4);
                ull d0 = pack2(x0, x0), d1 = pack2(x1, x1);
                a0 = fma2v(d0, k2.x, a0); a1 = fma2v(d0, k2.y, a1);
                c0 = fma2v(d1, k2.x, c0); c1 = fma2v(d1, k2.y, c1);
            }
            float2 A0 = unpack2(a0), A1 = unpack2(a1), C0 = unpack2(c0), C1 = unpack2(c1);
            float4 o0 = make_float4(A0.x * rn, A0.y * rn, A1.x * rn, A1.y * rn);
            float4 o1 = make_float4(C0.x * rn, C0.y * rn, C1.x * rn, C1.y * rn);
            *(float4*)(out + ((size_t)b * NT + t0) * EMB_ + ec * 4) = o0;
            *(float4*)(out + ((size_t)b * NT + t0 + 1) * EMB_ + ec * 4) = o1;
        }
    }
}

extern "C" void kernel_launch(void* const* d_in, const int* in_sizes, int n_in,
                              void* d_out, int out_size)
{
    const float* tvecs = (const float*)d_in[0];
    const float* cvecs = (const float*)d_in[1];
    const float* W_w   = (const float*)d_in[2];
    const float* W_b   = (const float*)d_in[3];
    const float* h_w   = (const float*)d_in[4];
    const float* h_b   = (const float*)d_in[5];
    const int*   ti    = (const int*)d_in[6];
    const int*   ci    = (const int*)d_in[7];
    const unsigned char* mask = (const unsigned char*)d_in[8];

    cudaFuncSetAttribute(nais_kernel, cudaFuncAttributeMaxDynamicSharedMemorySize, SMEM_BYTES);
    nais_kernel<<<B_, TPB, SMEM_BYTES>>>(tvecs, cvecs, W_w, W_b, h_w, h_b,
                                         ti, ci, mask, (float*)d_out);
}